// round 13
// baseline (speedup 1.0000x reference)
#include <cuda_runtime.h>
#include <cuda_bf16.h>
#include <math.h>

// Problem constants (fixed by the dataset)
#define N_NODES  100000
#define N_EDGES  1600000
#define N_FEAT   512
#define HIDDEN   128
#define N_CLASS  40

#define BCAP     128   // bucket slots per node; P(deg>=128) ~ e^-154 for this dataset

// ---------------- scratch (device globals; no cudaMalloc allowed) ------------
__device__ __align__(16) int      g_cnt   [N_NODES];
__device__ __align__(16) float    g_dinv  [N_NODES];
__device__ __align__(16) int      g_bucket[(size_t)N_NODES * BCAP];        // src idx, grouped by dst
__device__ __align__(16) unsigned g_hp  [(size_t)N_NODES * (HIDDEN / 2)];  // x@W1, bf16x2
__device__ __align__(16) unsigned g_a1p [(size_t)N_NODES * (HIDDEN / 2)];  // relu(agg1+b1), bf16x2
__device__ __align__(16) unsigned g_h2p [(size_t)N_NODES * (N_CLASS / 2)]; // dinv*(a1'@W2), bf16x2
__device__ __align__(16) float    g_a2  [(size_t)N_NODES * N_CLASS];       // aggregated logits fp32
__device__ int g_is64;

// ---------------- small helpers ----------------------------------------------
__device__ __forceinline__ void cp16(void* smem, const void* g, int sz) {
    unsigned sa = (unsigned)__cvta_generic_to_shared(smem);
    asm volatile("cp.async.cg.shared.global [%0], [%1], 16, %2;" :: "r"(sa), "l"(g), "r"(sz));
}
__device__ __forceinline__ void cp_commit() { asm volatile("cp.async.commit_group;"); }

__device__ __forceinline__ unsigned pack_bf16(float lo, float hi) {
    __nv_bfloat162 t = __float22bfloat162_rn(make_float2(lo, hi));
    return *reinterpret_cast<unsigned*>(&t);
}
__device__ __forceinline__ float2 unpack_bf16(unsigned u) {
    __nv_bfloat162 t = *reinterpret_cast<__nv_bfloat162*>(&u);
    return __bfloat1622float2(t);
}

// ---------------- init: detect dtype + zero counters ---------------------------
__global__ void k_init(const unsigned* __restrict__ ei_u32) {
    int i = blockIdx.x * blockDim.x + threadIdx.x;
    if (i < N_NODES) g_cnt[i] = 0;
    if (i == 0) {
        int all_zero = 1;
        #pragma unroll
        for (int j = 0; j < 8; j++)
            if (ei_u32[2 * j + 1] != 0u) all_zero = 0;
        g_is64 = all_zero;
    }
}

// bucket scatter: one pass builds the grouped-by-dst edge list (no scan needed)
__global__ void k_bucket(const void* __restrict__ ei_raw) {
    int e = blockIdx.x * blockDim.x + threadIdx.x;
    if (e >= N_EDGES) return;
    int s, d;
    if (g_is64) {
        const long long* ei = (const long long*)ei_raw;
        s = (int)ei[e];
        d = (int)ei[N_EDGES + e];
    } else {
        const int* ei = (const int*)ei_raw;
        s = ei[e];
        d = ei[N_EDGES + e];
    }
    int p = atomicAdd(&g_cnt[d], 1);
    if (p < BCAP) g_bucket[d * BCAP + p] = s;
}

// dinv from true degree (+1 self loop)
__global__ void k_dinv() {
    int i = blockIdx.x * blockDim.x + threadIdx.x;
    if (i < N_NODES) g_dinv[i] = rsqrtf((float)g_cnt[i] + 1.0f);
}

// ---------------- GEMM1 (tf32 mma + cp.async double buffer) -------------------
#define BM 128
#define BK 32
#define A_PAD 36
#define B_PAD 132
#define G1_SMEM ((2 * BM * A_PAD + 2 * BK * B_PAD) * 4)   // 70656 bytes

__device__ __forceinline__ void mma_tf32(float c[4], const unsigned a[4], const unsigned b[2]) {
    asm volatile(
        "mma.sync.aligned.m16n8k8.row.col.f32.tf32.tf32.f32 "
        "{%0,%1,%2,%3}, {%4,%5,%6,%7}, {%8,%9}, {%0,%1,%2,%3};"
        : "+f"(c[0]), "+f"(c[1]), "+f"(c[2]), "+f"(c[3])
        : "r"(a[0]), "r"(a[1]), "r"(a[2]), "r"(a[3]), "r"(b[0]), "r"(b[1]));
}

__global__ __launch_bounds__(256, 2) void k_gemm1_tc(const float* __restrict__ X,
                                                     const float* __restrict__ W) {
    extern __shared__ unsigned dynsmem[];
    unsigned* Asm = dynsmem;                      // [2][BM][A_PAD]
    unsigned* Bsm = dynsmem + 2 * BM * A_PAD;     // [2][BK][B_PAD]
    #define AS(b, m, k) Asm[(b) * BM * A_PAD + (m) * A_PAD + (k)]
    #define BS(b, k, n) Bsm[(b) * BK * B_PAD + (k) * B_PAD + (n)]

    const int tid = threadIdx.x;
    const int wid = tid >> 5;
    const int lane = tid & 31;
    const int g  = lane >> 2;
    const int tg = lane & 3;
    const int wm = wid >> 2;
    const int wn = wid & 3;
    const int mBase = wm * 64;
    const int nBase = wn * 32;
    const int rowBase = blockIdx.x * BM;

    float c[4][4][4];
    #pragma unroll
    for (int mi = 0; mi < 4; mi++)
        #pragma unroll
        for (int ni = 0; ni < 4; ni++)
            #pragma unroll
            for (int r = 0; r < 4; r++) c[mi][ni][r] = 0.0f;

    auto load_tiles = [&](int buf, int k0) {
        #pragma unroll
        for (int i = 0; i < 4; i++) {
            int slot = tid + i * 256;
            int m  = slot >> 3;
            int kq = slot & 7;
            int gr = rowBase + m;
            int valid = (gr < N_NODES);
            const float* src = X + (size_t)(valid ? gr : 0) * N_FEAT + k0 + kq * 4;
            cp16(&AS(buf, m, kq * 4), src, valid ? 16 : 0);
        }
        #pragma unroll
        for (int i = 0; i < 4; i++) {
            int slot = tid + i * 256;
            int kk = slot >> 5;
            int nq = slot & 31;
            cp16(&BS(buf, kk, nq * 4), W + (size_t)(k0 + kk) * HIDDEN + nq * 4, 16);
        }
        cp_commit();
    };

    load_tiles(0, 0);

    const int NIT = N_FEAT / BK;   // 16
    for (int it = 0; it < NIT; it++) {
        int cur = it & 1;
        if (it < NIT - 1) load_tiles(cur ^ 1, (it + 1) * BK);
        if (it < NIT - 1) { asm volatile("cp.async.wait_group 1;" ::: "memory"); }
        else              { asm volatile("cp.async.wait_group 0;" ::: "memory"); }
        __syncthreads();

        #pragma unroll
        for (int ks = 0; ks < 4; ks++) {
            const int kb = ks * 8;
            unsigned a[4][4];
            #pragma unroll
            for (int mi = 0; mi < 4; mi++) {
                int r0 = mBase + mi * 16 + g;
                a[mi][0] = AS(cur, r0,     kb + tg);
                a[mi][1] = AS(cur, r0 + 8, kb + tg);
                a[mi][2] = AS(cur, r0,     kb + tg + 4);
                a[mi][3] = AS(cur, r0 + 8, kb + tg + 4);
            }
            unsigned b[4][2];
            #pragma unroll
            for (int ni = 0; ni < 4; ni++) {
                int col = nBase + ni * 8 + g;
                b[ni][0] = BS(cur, kb + tg,     col);
                b[ni][1] = BS(cur, kb + tg + 4, col);
            }
            #pragma unroll
            for (int mi = 0; mi < 4; mi++)
                #pragma unroll
                for (int ni = 0; ni < 4; ni++)
                    mma_tf32(c[mi][ni], a[mi], b[ni]);
        }
        __syncthreads();
    }

    #pragma unroll
    for (int mi = 0; mi < 4; mi++) {
        int r0 = rowBase + mBase + mi * 16 + g;
        #pragma unroll
        for (int ni = 0; ni < 4; ni++) {
            int colu = (nBase + ni * 8) / 2 + tg;
            if (r0 < N_NODES)
                g_hp[(size_t)r0 * 64 + colu] = pack_bf16(c[mi][ni][0], c[mi][ni][1]);
            if (r0 + 8 < N_NODES)
                g_hp[(size_t)(r0 + 8) * 64 + colu] = pack_bf16(c[mi][ni][2], c[mi][ni][3]);
        }
    }
    #undef AS
    #undef BS
}

// ---------------- agg1: bucket gather, weight = dinv[s]; final *dinv[n] -------
__global__ __launch_bounds__(256) void k_agg1_g(const float* __restrict__ b1) {
    int t = blockIdx.x * blockDim.x + threadIdx.x;
    int n = t >> 5;
    if (n >= N_NODES) return;
    int lane = t & 31;

    float wn = g_dinv[n];

    uint2 su = *(const uint2*)&g_hp[(size_t)n * 64 + 2 * lane];
    float2 s0 = unpack_bf16(su.x), s1 = unpack_bf16(su.y);
    float4 acc = make_float4(s0.x * wn, s0.y * wn, s1.x * wn, s1.y * wn);

    const int* bkt = &g_bucket[n * BCAP];
    int cnt = g_cnt[n];
    int end = (cnt < BCAP) ? cnt : BCAP;
    int e = 0;

    for (; e + 4 <= end; e += 4) {
        int i0 = bkt[e], i1 = bkt[e + 1], i2 = bkt[e + 2], i3 = bkt[e + 3];
        float w0 = g_dinv[i0], w1 = g_dinv[i1], w2 = g_dinv[i2], w3 = g_dinv[i3];
        uint2 u0 = *(const uint2*)&g_hp[(size_t)i0 * 64 + 2 * lane];
        uint2 u1 = *(const uint2*)&g_hp[(size_t)i1 * 64 + 2 * lane];
        uint2 u2 = *(const uint2*)&g_hp[(size_t)i2 * 64 + 2 * lane];
        uint2 u3 = *(const uint2*)&g_hp[(size_t)i3 * 64 + 2 * lane];
        float2 a, b;
        a = unpack_bf16(u0.x); b = unpack_bf16(u0.y);
        acc.x = fmaf(a.x, w0, acc.x); acc.y = fmaf(a.y, w0, acc.y);
        acc.z = fmaf(b.x, w0, acc.z); acc.w = fmaf(b.y, w0, acc.w);
        a = unpack_bf16(u1.x); b = unpack_bf16(u1.y);
        acc.x = fmaf(a.x, w1, acc.x); acc.y = fmaf(a.y, w1, acc.y);
        acc.z = fmaf(b.x, w1, acc.z); acc.w = fmaf(b.y, w1, acc.w);
        a = unpack_bf16(u2.x); b = unpack_bf16(u2.y);
        acc.x = fmaf(a.x, w2, acc.x); acc.y = fmaf(a.y, w2, acc.y);
        acc.z = fmaf(b.x, w2, acc.z); acc.w = fmaf(b.y, w2, acc.w);
        a = unpack_bf16(u3.x); b = unpack_bf16(u3.y);
        acc.x = fmaf(a.x, w3, acc.x); acc.y = fmaf(a.y, w3, acc.y);
        acc.z = fmaf(b.x, w3, acc.z); acc.w = fmaf(b.y, w3, acc.w);
    }
    for (; e < end; e++) {
        int i0 = bkt[e];
        float w0 = g_dinv[i0];
        uint2 u0 = *(const uint2*)&g_hp[(size_t)i0 * 64 + 2 * lane];
        float2 a = unpack_bf16(u0.x), b = unpack_bf16(u0.y);
        acc.x = fmaf(a.x, w0, acc.x); acc.y = fmaf(a.y, w0, acc.y);
        acc.z = fmaf(b.x, w0, acc.z); acc.w = fmaf(b.y, w0, acc.w);
    }

    float4 bv = *(const float4*)&b1[lane * 4];
    acc.x = fmaxf(fmaf(acc.x, wn, bv.x), 0.0f);
    acc.y = fmaxf(fmaf(acc.y, wn, bv.y), 0.0f);
    acc.z = fmaxf(fmaf(acc.z, wn, bv.z), 0.0f);
    acc.w = fmaxf(fmaf(acc.w, wn, bv.w), 0.0f);

    uint2 o;
    o.x = pack_bf16(acc.x, acc.y);
    o.y = pack_bf16(acc.z, acc.w);
    *(uint2*)&g_a1p[(size_t)n * 64 + 2 * lane] = o;
}

// ---------------- GEMM2 (bf16 mma): g_h2p = dinv * (a1' @ W2) ------------------
#define A2_PAD 68
__global__ __launch_bounds__(256) void k_gemm2_tc(const float* __restrict__ W2) {
    __shared__ unsigned sAp[128][A2_PAD];
    __shared__ unsigned sBp[64][N_CLASS];

    const int tid = threadIdx.x;
    const int wid = tid >> 5;
    const int lane = tid & 31;
    const int g  = lane >> 2;
    const int tg = lane & 3;
    const int rowBase = blockIdx.x * 128;

    for (int i = tid; i < 64 * N_CLASS; i += 256) {
        int k2 = i / N_CLASS, n = i % N_CLASS;
        float lo = W2[(size_t)(2 * k2) * N_CLASS + n];
        float hi = W2[(size_t)(2 * k2 + 1) * N_CLASS + n];
        sBp[k2][n] = pack_bf16(lo, hi);
    }
    #pragma unroll
    for (int i = 0; i < 8; i++) {
        int slot = tid + i * 256;
        int m = slot >> 4;
        int j = slot & 15;
        int gr = rowBase + m;
        int valid = (gr < N_NODES);
        cp16(&sAp[m][j * 4], g_a1p + (size_t)(valid ? gr : 0) * 64 + j * 4, valid ? 16 : 0);
    }
    cp_commit();
    asm volatile("cp.async.wait_group 0;" ::: "memory");
    __syncthreads();

    const int mBase = wid * 16;
    float c[5][4];
    #pragma unroll
    for (int ni = 0; ni < 5; ni++)
        #pragma unroll
        for (int r = 0; r < 4; r++) c[ni][r] = 0.0f;

    #pragma unroll
    for (int ks = 0; ks < 8; ks++) {
        int k2b = ks * 8;
        int r0 = mBase + g;
        unsigned a0 = sAp[r0    ][k2b + tg];
        unsigned a1 = sAp[r0 + 8][k2b + tg];
        unsigned a2 = sAp[r0    ][k2b + tg + 4];
        unsigned a3 = sAp[r0 + 8][k2b + tg + 4];
        #pragma unroll
        for (int ni = 0; ni < 5; ni++) {
            unsigned b0 = sBp[k2b + tg    ][ni * 8 + g];
            unsigned b1r = sBp[k2b + tg + 4][ni * 8 + g];
            asm volatile(
                "mma.sync.aligned.m16n8k16.row.col.f32.bf16.bf16.f32 "
                "{%0,%1,%2,%3}, {%4,%5,%6,%7}, {%8,%9}, {%0,%1,%2,%3};"
                : "+f"(c[ni][0]), "+f"(c[ni][1]), "+f"(c[ni][2]), "+f"(c[ni][3])
                : "r"(a0), "r"(a1), "r"(a2), "r"(a3), "r"(b0), "r"(b1r));
        }
    }

    int r0 = rowBase + mBase + g;
    float w0 = (r0 < N_NODES) ? g_dinv[r0] : 0.0f;
    float w1 = (r0 + 8 < N_NODES) ? g_dinv[r0 + 8] : 0.0f;
    #pragma unroll
    for (int ni = 0; ni < 5; ni++) {
        int colu = ni * 4 + tg;
        if (r0 < N_NODES)
            g_h2p[(size_t)r0 * 20 + colu] = pack_bf16(c[ni][0] * w0, c[ni][1] * w0);
        if (r0 + 8 < N_NODES)
            g_h2p[(size_t)(r0 + 8) * 20 + colu] = pack_bf16(c[ni][2] * w1, c[ni][3] * w1);
    }
}

// ---------------- agg2: bucket gather on pre-scaled h2', 10 threads/node ------
__global__ __launch_bounds__(256) void k_agg2_g() {
    int t = blockIdx.x * blockDim.x + threadIdx.x;
    int n = t / 10;
    if (n >= N_NODES) return;
    int q = t % 10;

    float wn = g_dinv[n];

    uint2 su = *(const uint2*)&g_h2p[(size_t)n * 20 + 2 * q];
    float2 s0 = unpack_bf16(su.x), s1 = unpack_bf16(su.y);
    float4 acc = make_float4(s0.x, s0.y, s1.x, s1.y);

    const int* bkt = &g_bucket[n * BCAP];
    int cnt = g_cnt[n];
    int end = (cnt < BCAP) ? cnt : BCAP;
    int e = 0;
    for (; e + 2 <= end; e += 2) {
        int i0 = bkt[e], i1 = bkt[e + 1];
        uint2 u0 = *(const uint2*)&g_h2p[(size_t)i0 * 20 + 2 * q];
        uint2 u1 = *(const uint2*)&g_h2p[(size_t)i1 * 20 + 2 * q];
        float2 a = unpack_bf16(u0.x), b = unpack_bf16(u0.y);
        acc.x += a.x; acc.y += a.y; acc.z += b.x; acc.w += b.y;
        a = unpack_bf16(u1.x); b = unpack_bf16(u1.y);
        acc.x += a.x; acc.y += a.y; acc.z += b.x; acc.w += b.y;
    }
    if (e < end) {
        int i0 = bkt[e];
        uint2 u0 = *(const uint2*)&g_h2p[(size_t)i0 * 20 + 2 * q];
        float2 a = unpack_bf16(u0.x), b = unpack_bf16(u0.y);
        acc.x += a.x; acc.y += a.y; acc.z += b.x; acc.w += b.y;
    }
    acc.x *= wn; acc.y *= wn; acc.z *= wn; acc.w *= wn;
    *(float4*)&g_a2[(size_t)n * N_CLASS + q * 4] = acc;
}

// ---------------- log_softmax(a2 + b2) -> out --------------------------------
__global__ void k_lsm(const float* __restrict__ b2, float* __restrict__ out) {
    int r = blockIdx.x * 4 + (threadIdx.x >> 5);
    if (r >= N_NODES) return;
    int lane = threadIdx.x & 31;

    float x0 = g_a2[(size_t)r * N_CLASS + lane] + b2[lane];
    float x1 = -1e30f;
    if (lane < 8) x1 = g_a2[(size_t)r * N_CLASS + 32 + lane] + b2[32 + lane];

    float m = fmaxf(x0, x1);
    #pragma unroll
    for (int o = 16; o > 0; o >>= 1) m = fmaxf(m, __shfl_xor_sync(0xFFFFFFFFu, m, o));

    float s = expf(x0 - m) + ((lane < 8) ? expf(x1 - m) : 0.0f);
    #pragma unroll
    for (int o = 16; o > 0; o >>= 1) s += __shfl_xor_sync(0xFFFFFFFFu, s, o);

    float ls = m + logf(s);
    out[(size_t)r * N_CLASS + lane] = x0 - ls;
    if (lane < 8) out[(size_t)r * N_CLASS + 32 + lane] = x1 - ls;
}

// ---------------- launcher: fork-join (prep || gemm1) --------------------------
extern "C" void kernel_launch(void* const* d_in, const int* in_sizes, int n_in,
                              void* d_out, int out_size) {
    const float* x  = (const float*)d_in[0];
    const void*  ei = d_in[1];
    const float* W1 = (const float*)d_in[2];
    const float* b1 = (const float*)d_in[3];
    const float* W2 = (const float*)d_in[4];
    const float* b2 = (const float*)d_in[5];
    float* out = (float*)d_out;

    static cudaStream_t s_prep = nullptr;
    static cudaEvent_t ev_fork = nullptr, ev_join = nullptr;
    if (s_prep == nullptr) {
        cudaStreamCreateWithFlags(&s_prep, cudaStreamNonBlocking);
        cudaEventCreateWithFlags(&ev_fork, cudaEventDisableTiming);
        cudaEventCreateWithFlags(&ev_join, cudaEventDisableTiming);
        cudaFuncSetAttribute(k_gemm1_tc, cudaFuncAttributeMaxDynamicSharedMemorySize, G1_SMEM);
    }

    // fork: prep chain (3 kernels, no scan) on side stream, gemm1 on main stream
    cudaEventRecord(ev_fork, 0);
    cudaStreamWaitEvent(s_prep, ev_fork, 0);

    k_init<<<(N_NODES + 255) / 256, 256, 0, s_prep>>>((const unsigned*)ei);
    k_bucket<<<(N_EDGES + 255) / 256, 256, 0, s_prep>>>(ei);
    k_dinv<<<(N_NODES + 255) / 256, 256, 0, s_prep>>>();

    k_gemm1_tc<<<(N_NODES + BM - 1) / BM, 256, G1_SMEM>>>(x, W1);

    // join
    cudaEventRecord(ev_join, s_prep);
    cudaStreamWaitEvent(0, ev_join, 0);

    k_agg1_g<<<(N_NODES * 32 + 255) / 256, 256>>>(b1);
    k_gemm2_tc<<<(N_NODES + 127) / 128, 256>>>(W2);
    k_agg2_g<<<(N_NODES * 10 + 255) / 256, 256>>>();
    k_lsm<<<(N_NODES + 3) / 4, 128>>>(b2, out);
}

// round 15
// speedup vs baseline: 1.0276x; 1.0276x over previous
#include <cuda_runtime.h>
#include <cuda_bf16.h>
#include <math.h>

// Problem constants (fixed by the dataset)
#define N_NODES  100000
#define N_EDGES  1600000
#define N_FEAT   512
#define HIDDEN   128
#define N_CLASS  40

#define BCAP     128   // bucket slots per node; P(deg>=128) ~ e^-154 for this dataset

// ---------------- scratch (device globals; no cudaMalloc allowed) ------------
__device__ __align__(16) int      g_cnt   [N_NODES];
__device__ __align__(16) float    g_dinv  [N_NODES];
__device__ __align__(16) int      g_bucket[(size_t)N_NODES * BCAP];        // src idx, grouped by dst
__device__ __align__(16) float    g_wt    [HIDDEN * N_FEAT];               // W1^T [128][512]
__device__ __align__(16) unsigned g_hp  [(size_t)N_NODES * (HIDDEN / 2)];  // x@W1, bf16x2
__device__ __align__(16) unsigned g_a1p [(size_t)N_NODES * (HIDDEN / 2)];  // relu(agg1+b1), bf16x2
__device__ __align__(16) unsigned g_h2p [(size_t)N_NODES * (N_CLASS / 2)]; // dinv*(a1'@W2), bf16x2
__device__ __align__(16) float    g_a2  [(size_t)N_NODES * N_CLASS];       // aggregated logits fp32
__device__ int g_is64;

// ---------------- small helpers ----------------------------------------------
__device__ __forceinline__ void cp16(void* smem, const void* g, int sz) {
    unsigned sa = (unsigned)__cvta_generic_to_shared(smem);
    asm volatile("cp.async.cg.shared.global [%0], [%1], 16, %2;" :: "r"(sa), "l"(g), "r"(sz));
}
__device__ __forceinline__ void cp_commit() { asm volatile("cp.async.commit_group;"); }

__device__ __forceinline__ unsigned pack_bf16(float lo, float hi) {
    __nv_bfloat162 t = __float22bfloat162_rn(make_float2(lo, hi));
    return *reinterpret_cast<unsigned*>(&t);
}
__device__ __forceinline__ float2 unpack_bf16(unsigned u) {
    __nv_bfloat162 t = *reinterpret_cast<__nv_bfloat162*>(&u);
    return __bfloat1622float2(t);
}

#define LDSM4(r0, r1, r2, r3, addr) \
    asm volatile("ldmatrix.sync.aligned.m8n8.x4.shared.b16 {%0,%1,%2,%3}, [%4];" \
                 : "=r"(r0), "=r"(r1), "=r"(r2), "=r"(r3) : "r"(addr))
#define LDSM2(r0, r1, addr) \
    asm volatile("ldmatrix.sync.aligned.m8n8.x2.shared.b16 {%0,%1}, [%2];" \
                 : "=r"(r0), "=r"(r1) : "r"(addr))

// ---------------- init: detect dtype + zero counters ---------------------------
__global__ void k_init(const unsigned* __restrict__ ei_u32) {
    int i = blockIdx.x * blockDim.x + threadIdx.x;
    if (i < N_NODES) g_cnt[i] = 0;
    if (i == 0) {
        int all_zero = 1;
        #pragma unroll
        for (int j = 0; j < 8; j++)
            if (ei_u32[2 * j + 1] != 0u) all_zero = 0;
        g_is64 = all_zero;
    }
}

// bucket scatter: one pass builds the grouped-by-dst edge list (no scan needed)
__global__ void k_bucket(const void* __restrict__ ei_raw) {
    int e = blockIdx.x * blockDim.x + threadIdx.x;
    if (e >= N_EDGES) return;
    int s, d;
    if (g_is64) {
        const long long* ei = (const long long*)ei_raw;
        s = (int)ei[e];
        d = (int)ei[N_EDGES + e];
    } else {
        const int* ei = (const int*)ei_raw;
        s = ei[e];
        d = ei[N_EDGES + e];
    }
    int p = atomicAdd(&g_cnt[d], 1);
    if (p < BCAP) g_bucket[d * BCAP + p] = s;
}

// dinv from true degree (+1 self loop)
__global__ void k_dinv() {
    int i = blockIdx.x * blockDim.x + threadIdx.x;
    if (i < N_NODES) g_dinv[i] = rsqrtf((float)g_cnt[i] + 1.0f);
}

// transpose W1 -> Wt[n][k]  (n-major, so B fragments map to ldmatrix directly)
__global__ void k_wt(const float* __restrict__ W) {
    int i = blockIdx.x * blockDim.x + threadIdx.x;   // over 128*512
    if (i >= HIDDEN * N_FEAT) return;
    int n = i >> 9;    // /512
    int k = i & 511;
    g_wt[i] = W[k * HIDDEN + n];
}

// ---------------- GEMM1 (tf32 mma + cp.async + ldmatrix fragments) ------------
#define BM 128
#define BK 32
#define A_PAD 36
#define TILE_WORDS (BM * A_PAD)               // 4608 words per tile
#define G1_SMEM (4 * TILE_WORDS * 4)          // 2 bufs x (A + B) = 73728 bytes

__device__ __forceinline__ void mma_tf32(float c[4], const unsigned a[4], const unsigned b[2]) {
    asm volatile(
        "mma.sync.aligned.m16n8k8.row.col.f32.tf32.tf32.f32 "
        "{%0,%1,%2,%3}, {%4,%5,%6,%7}, {%8,%9}, {%0,%1,%2,%3};"
        : "+f"(c[0]), "+f"(c[1]), "+f"(c[2]), "+f"(c[3])
        : "r"(a[0]), "r"(a[1]), "r"(a[2]), "r"(a[3]), "r"(b[0]), "r"(b[1]));
}

__global__ __launch_bounds__(256, 2) void k_gemm1_tc(const float* __restrict__ X) {
    extern __shared__ unsigned dynsmem[];
    // words: A(buf) at buf*2*TILE_WORDS, B(buf) at buf*2*TILE_WORDS + TILE_WORDS
    #define AW(buf) (dynsmem + (buf) * 2 * TILE_WORDS)
    #define BW(buf) (dynsmem + (buf) * 2 * TILE_WORDS + TILE_WORDS)

    const int tid = threadIdx.x;
    const int wid = tid >> 5;
    const int lane = tid & 31;
    const int g  = lane >> 2;
    const int tg = lane & 3;
    const int wm = wid >> 2;
    const int wn = wid & 3;
    const int mBase = wm * 64;
    const int nBase = wn * 32;
    const int rowBase = blockIdx.x * BM;

    const unsigned sbase = (unsigned)__cvta_generic_to_shared(dynsmem);
    unsigned aTile[2] = {sbase, sbase + 2 * TILE_WORDS * 4};
    unsigned bTile[2] = {sbase + TILE_WORDS * 4, sbase + 3 * TILE_WORDS * 4};

    // ldmatrix per-lane offsets (bytes within tile)
    const int sel  = lane >> 3;          // 0..3 (x4 matrix id)
    const int rlo  = lane & 7;
    unsigned offA[4];
    #pragma unroll
    for (int mi = 0; mi < 4; mi++) {
        int row = mBase + mi * 16 + (sel & 1) * 8 + rlo;
        int col = (sel >> 1) * 4;
        offA[mi] = (unsigned)(row * A_PAD + col) * 4;
    }
    const int l2 = lane & 15;            // x2 uses lanes 0..15
    const int selb = l2 >> 3;
    const int rb = l2 & 7;
    unsigned offB[4];
    #pragma unroll
    for (int ni = 0; ni < 4; ni++) {
        int row = nBase + ni * 8 + rb;   // n index (Bs is n-major)
        int col = selb * 4;
        offB[ni] = (unsigned)(row * A_PAD + col) * 4;
    }

    float c[4][4][4];
    #pragma unroll
    for (int mi = 0; mi < 4; mi++)
        #pragma unroll
        for (int ni = 0; ni < 4; ni++)
            #pragma unroll
            for (int r = 0; r < 4; r++) c[mi][ni][r] = 0.0f;

    auto load_tiles = [&](int buf, int k0) {
        #pragma unroll
        for (int i = 0; i < 4; i++) {
            int slot = tid + i * 256;
            int m  = slot >> 3;
            int kq = slot & 7;
            int gr = rowBase + m;
            int valid = (gr < N_NODES);
            const float* src = X + (size_t)(valid ? gr : 0) * N_FEAT + k0 + kq * 4;
            cp16(AW(buf) + m * A_PAD + kq * 4, src, valid ? 16 : 0);
        }
        #pragma unroll
        for (int i = 0; i < 4; i++) {
            int slot = tid + i * 256;
            int n  = slot >> 3;
            int kq = slot & 7;
            cp16(BW(buf) + n * A_PAD + kq * 4, g_wt + (size_t)n * N_FEAT + k0 + kq * 4, 16);
        }
        cp_commit();
    };

    load_tiles(0, 0);

    const int NIT = N_FEAT / BK;   // 16
    for (int it = 0; it < NIT; it++) {
        int cur = it & 1;
        if (it < NIT - 1) load_tiles(cur ^ 1, (it + 1) * BK);
        if (it < NIT - 1) { asm volatile("cp.async.wait_group 1;" ::: "memory"); }
        else              { asm volatile("cp.async.wait_group 0;" ::: "memory"); }
        __syncthreads();

        #pragma unroll
        for (int ks = 0; ks < 4; ks++) {
            const unsigned kbB = ks * 32;   // 8 words = 32 bytes
            unsigned a[4][4];
            #pragma unroll
            for (int mi = 0; mi < 4; mi++)
                LDSM4(a[mi][0], a[mi][1], a[mi][2], a[mi][3], aTile[cur] + offA[mi] + kbB);
            unsigned b[4][2];
            #pragma unroll
            for (int ni = 0; ni < 4; ni++)
                LDSM2(b[ni][0], b[ni][1], bTile[cur] + offB[ni] + kbB);
            #pragma unroll
            for (int mi = 0; mi < 4; mi++)
                #pragma unroll
                for (int ni = 0; ni < 4; ni++)
                    mma_tf32(c[mi][ni], a[mi], b[ni]);
        }
        __syncthreads();
    }

    #pragma unroll
    for (int mi = 0; mi < 4; mi++) {
        int r0 = rowBase + mBase + mi * 16 + g;
        #pragma unroll
        for (int ni = 0; ni < 4; ni++) {
            int colu = (nBase + ni * 8) / 2 + tg;
            if (r0 < N_NODES)
                g_hp[(size_t)r0 * 64 + colu] = pack_bf16(c[mi][ni][0], c[mi][ni][1]);
            if (r0 + 8 < N_NODES)
                g_hp[(size_t)(r0 + 8) * 64 + colu] = pack_bf16(c[mi][ni][2], c[mi][ni][3]);
        }
    }
    #undef AW
    #undef BW
}

// ---------------- agg1: bucket gather, weight = dinv[s]; final *dinv[n] -------
__global__ __launch_bounds__(256) void k_agg1_g(const float* __restrict__ b1) {
    int t = blockIdx.x * blockDim.x + threadIdx.x;
    int n = t >> 5;
    if (n >= N_NODES) return;
    int lane = t & 31;

    float wn = g_dinv[n];

    uint2 su = *(const uint2*)&g_hp[(size_t)n * 64 + 2 * lane];
    float2 s0 = unpack_bf16(su.x), s1 = unpack_bf16(su.y);
    float4 acc = make_float4(s0.x * wn, s0.y * wn, s1.x * wn, s1.y * wn);

    const int* bkt = &g_bucket[n * BCAP];
    int cnt = g_cnt[n];
    int end = (cnt < BCAP) ? cnt : BCAP;
    int e = 0;

    for (; e + 4 <= end; e += 4) {
        int i0 = bkt[e], i1 = bkt[e + 1], i2 = bkt[e + 2], i3 = bkt[e + 3];
        float w0 = g_dinv[i0], w1 = g_dinv[i1], w2 = g_dinv[i2], w3 = g_dinv[i3];
        uint2 u0 = *(const uint2*)&g_hp[(size_t)i0 * 64 + 2 * lane];
        uint2 u1 = *(const uint2*)&g_hp[(size_t)i1 * 64 + 2 * lane];
        uint2 u2 = *(const uint2*)&g_hp[(size_t)i2 * 64 + 2 * lane];
        uint2 u3 = *(const uint2*)&g_hp[(size_t)i3 * 64 + 2 * lane];
        float2 a, b;
        a = unpack_bf16(u0.x); b = unpack_bf16(u0.y);
        acc.x = fmaf(a.x, w0, acc.x); acc.y = fmaf(a.y, w0, acc.y);
        acc.z = fmaf(b.x, w0, acc.z); acc.w = fmaf(b.y, w0, acc.w);
        a = unpack_bf16(u1.x); b = unpack_bf16(u1.y);
        acc.x = fmaf(a.x, w1, acc.x); acc.y = fmaf(a.y, w1, acc.y);
        acc.z = fmaf(b.x, w1, acc.z); acc.w = fmaf(b.y, w1, acc.w);
        a = unpack_bf16(u2.x); b = unpack_bf16(u2.y);
        acc.x = fmaf(a.x, w2, acc.x); acc.y = fmaf(a.y, w2, acc.y);
        acc.z = fmaf(b.x, w2, acc.z); acc.w = fmaf(b.y, w2, acc.w);
        a = unpack_bf16(u3.x); b = unpack_bf16(u3.y);
        acc.x = fmaf(a.x, w3, acc.x); acc.y = fmaf(a.y, w3, acc.y);
        acc.z = fmaf(b.x, w3, acc.z); acc.w = fmaf(b.y, w3, acc.w);
    }
    for (; e < end; e++) {
        int i0 = bkt[e];
        float w0 = g_dinv[i0];
        uint2 u0 = *(const uint2*)&g_hp[(size_t)i0 * 64 + 2 * lane];
        float2 a = unpack_bf16(u0.x), b = unpack_bf16(u0.y);
        acc.x = fmaf(a.x, w0, acc.x); acc.y = fmaf(a.y, w0, acc.y);
        acc.z = fmaf(b.x, w0, acc.z); acc.w = fmaf(b.y, w0, acc.w);
    }

    float4 bv = *(const float4*)&b1[lane * 4];
    acc.x = fmaxf(fmaf(acc.x, wn, bv.x), 0.0f);
    acc.y = fmaxf(fmaf(acc.y, wn, bv.y), 0.0f);
    acc.z = fmaxf(fmaf(acc.z, wn, bv.z), 0.0f);
    acc.w = fmaxf(fmaf(acc.w, wn, bv.w), 0.0f);

    uint2 o;
    o.x = pack_bf16(acc.x, acc.y);
    o.y = pack_bf16(acc.z, acc.w);
    *(uint2*)&g_a1p[(size_t)n * 64 + 2 * lane] = o;
}

// ---------------- GEMM2 (bf16 mma): g_h2p = dinv * (a1' @ W2) ------------------
#define A2_PAD 68
__global__ __launch_bounds__(256) void k_gemm2_tc(const float* __restrict__ W2) {
    __shared__ unsigned sAp[128][A2_PAD];
    __shared__ unsigned sBp[64][N_CLASS];

    const int tid = threadIdx.x;
    const int wid = tid >> 5;
    const int lane = tid & 31;
    const int g  = lane >> 2;
    const int tg = lane & 3;
    const int rowBase = blockIdx.x * 128;

    for (int i = tid; i < 64 * N_CLASS; i += 256) {
        int k2 = i / N_CLASS, n = i % N_CLASS;
        float lo = W2[(size_t)(2 * k2) * N_CLASS + n];
        float hi = W2[(size_t)(2 * k2 + 1) * N_CLASS + n];
        sBp[k2][n] = pack_bf16(lo, hi);
    }
    #pragma unroll
    for (int i = 0; i < 8; i++) {
        int slot = tid + i * 256;
        int m = slot >> 4;
        int j = slot & 15;
        int gr = rowBase + m;
        int valid = (gr < N_NODES);
        cp16(&sAp[m][j * 4], g_a1p + (size_t)(valid ? gr : 0) * 64 + j * 4, valid ? 16 : 0);
    }
    cp_commit();
    asm volatile("cp.async.wait_group 0;" ::: "memory");
    __syncthreads();

    const int mBase = wid * 16;
    float c[5][4];
    #pragma unroll
    for (int ni = 0; ni < 5; ni++)
        #pragma unroll
        for (int r = 0; r < 4; r++) c[ni][r] = 0.0f;

    #pragma unroll
    for (int ks = 0; ks < 8; ks++) {
        int k2b = ks * 8;
        int r0 = mBase + g;
        unsigned a0 = sAp[r0    ][k2b + tg];
        unsigned a1 = sAp[r0 + 8][k2b + tg];
        unsigned a2 = sAp[r0    ][k2b + tg + 4];
        unsigned a3 = sAp[r0 + 8][k2b + tg + 4];
        #pragma unroll
        for (int ni = 0; ni < 5; ni++) {
            unsigned b0 = sBp[k2b + tg    ][ni * 8 + g];
            unsigned b1r = sBp[k2b + tg + 4][ni * 8 + g];
            asm volatile(
                "mma.sync.aligned.m16n8k16.row.col.f32.bf16.bf16.f32 "
                "{%0,%1,%2,%3}, {%4,%5,%6,%7}, {%8,%9}, {%0,%1,%2,%3};"
                : "+f"(c[ni][0]), "+f"(c[ni][1]), "+f"(c[ni][2]), "+f"(c[ni][3])
                : "r"(a0), "r"(a1), "r"(a2), "r"(a3), "r"(b0), "r"(b1r));
        }
    }

    int r0 = rowBase + mBase + g;
    float w0 = (r0 < N_NODES) ? g_dinv[r0] : 0.0f;
    float w1 = (r0 + 8 < N_NODES) ? g_dinv[r0 + 8] : 0.0f;
    #pragma unroll
    for (int ni = 0; ni < 5; ni++) {
        int colu = ni * 4 + tg;
        if (r0 < N_NODES)
            g_h2p[(size_t)r0 * 20 + colu] = pack_bf16(c[ni][0] * w0, c[ni][1] * w0);
        if (r0 + 8 < N_NODES)
            g_h2p[(size_t)(r0 + 8) * 20 + colu] = pack_bf16(c[ni][2] * w1, c[ni][3] * w1);
    }
}

// ---------------- agg2: bucket gather on pre-scaled h2', 10 threads/node ------
__global__ __launch_bounds__(256) void k_agg2_g() {
    int t = blockIdx.x * blockDim.x + threadIdx.x;
    int n = t / 10;
    if (n >= N_NODES) return;
    int q = t % 10;

    float wn = g_dinv[n];

    uint2 su = *(const uint2*)&g_h2p[(size_t)n * 20 + 2 * q];
    float2 s0 = unpack_bf16(su.x), s1 = unpack_bf16(su.y);
    float4 acc = make_float4(s0.x, s0.y, s1.x, s1.y);

    const int* bkt = &g_bucket[n * BCAP];
    int cnt = g_cnt[n];
    int end = (cnt < BCAP) ? cnt : BCAP;
    int e = 0;
    for (; e + 2 <= end; e += 2) {
        int i0 = bkt[e], i1 = bkt[e + 1];
        uint2 u0 = *(const uint2*)&g_h2p[(size_t)i0 * 20 + 2 * q];
        uint2 u1 = *(const uint2*)&g_h2p[(size_t)i1 * 20 + 2 * q];
        float2 a = unpack_bf16(u0.x), b = unpack_bf16(u0.y);
        acc.x += a.x; acc.y += a.y; acc.z += b.x; acc.w += b.y;
        a = unpack_bf16(u1.x); b = unpack_bf16(u1.y);
        acc.x += a.x; acc.y += a.y; acc.z += b.x; acc.w += b.y;
    }
    if (e < end) {
        int i0 = bkt[e];
        uint2 u0 = *(const uint2*)&g_h2p[(size_t)i0 * 20 + 2 * q];
        float2 a = unpack_bf16(u0.x), b = unpack_bf16(u0.y);
        acc.x += a.x; acc.y += a.y; acc.z += b.x; acc.w += b.y;
    }
    acc.x *= wn; acc.y *= wn; acc.z *= wn; acc.w *= wn;
    *(float4*)&g_a2[(size_t)n * N_CLASS + q * 4] = acc;
}

// ---------------- log_softmax(a2 + b2) -> out --------------------------------
__global__ void k_lsm(const float* __restrict__ b2, float* __restrict__ out) {
    int r = blockIdx.x * 4 + (threadIdx.x >> 5);
    if (r >= N_NODES) return;
    int lane = threadIdx.x & 31;

    float x0 = g_a2[(size_t)r * N_CLASS + lane] + b2[lane];
    float x1 = -1e30f;
    if (lane < 8) x1 = g_a2[(size_t)r * N_CLASS + 32 + lane] + b2[32 + lane];

    float m = fmaxf(x0, x1);
    #pragma unroll
    for (int o = 16; o > 0; o >>= 1) m = fmaxf(m, __shfl_xor_sync(0xFFFFFFFFu, m, o));

    float s = expf(x0 - m) + ((lane < 8) ? expf(x1 - m) : 0.0f);
    #pragma unroll
    for (int o = 16; o > 0; o >>= 1) s += __shfl_xor_sync(0xFFFFFFFFu, s, o);

    float ls = m + logf(s);
    out[(size_t)r * N_CLASS + lane] = x0 - ls;
    if (lane < 8) out[(size_t)r * N_CLASS + 32 + lane] = x1 - ls;
}

// ---------------- launcher: fork-join (prep || gemm1) --------------------------
extern "C" void kernel_launch(void* const* d_in, const int* in_sizes, int n_in,
                              void* d_out, int out_size) {
    const float* x  = (const float*)d_in[0];
    const void*  ei = d_in[1];
    const float* W1 = (const float*)d_in[2];
    const float* b1 = (const float*)d_in[3];
    const float* W2 = (const float*)d_in[4];
    const float* b2 = (const float*)d_in[5];
    float* out = (float*)d_out;

    static cudaStream_t s_prep = nullptr;
    static cudaEvent_t ev_fork = nullptr, ev_join = nullptr;
    if (s_prep == nullptr) {
        cudaStreamCreateWithFlags(&s_prep, cudaStreamNonBlocking);
        cudaEventCreateWithFlags(&ev_fork, cudaEventDisableTiming);
        cudaEventCreateWithFlags(&ev_join, cudaEventDisableTiming);
        cudaFuncSetAttribute(k_gemm1_tc, cudaFuncAttributeMaxDynamicSharedMemorySize, G1_SMEM);
    }

    // fork: prep chain (3 kernels, no scan) on side stream, W1-transpose + gemm1 on main
    cudaEventRecord(ev_fork, 0);
    cudaStreamWaitEvent(s_prep, ev_fork, 0);

    k_init<<<(N_NODES + 255) / 256, 256, 0, s_prep>>>((const unsigned*)ei);
    k_bucket<<<(N_EDGES + 255) / 256, 256, 0, s_prep>>>(ei);
    k_dinv<<<(N_NODES + 255) / 256, 256, 0, s_prep>>>();

    k_wt<<<(HIDDEN * N_FEAT + 255) / 256, 256>>>(W1);
    k_gemm1_tc<<<(N_NODES + BM - 1) / BM, 256, G1_SMEM>>>(x);

    // join
    cudaEventRecord(ev_join, s_prep);
    cudaStreamWaitEvent(0, ev_join, 0);

    k_agg1_g<<<(N_NODES * 32 + 255) / 256, 256>>>(b1);
    k_gemm2_tc<<<(N_NODES + 127) / 128, 256>>>(W2);
    k_agg2_g<<<(N_NODES * 10 + 255) / 256, 256>>>();
    k_lsm<<<(N_NODES + 3) / 4, 128>>>(b2, out);
}